// round 9
// baseline (speedup 1.0000x reference)
#include <cuda_runtime.h>
#include <cuda_bf16.h>
#include <cstdint>

#define H            128
#define BASKET_LEN   200
#define NT           1024          // 32 warps per block
#define WARPS        32
#define GATHER_BLKS  7             // 7*32 = 224 warps >= 200 items
#define NB           (GATHER_BLKS + 1)   // block 7 = dedicated tail

// Device-global scratch (no allocation). Every slot rewritten each launch.
__device__ float        g_part[GATHER_BLKS][H];
__device__ unsigned int g_ticket;   // zero at load; reset by tail each launch

__device__ __forceinline__ float fast_sigmoid(float x) {
    return __fdividef(1.0f, 1.0f + __expf(-x));
}
__device__ __forceinline__ float fast_tanh(float x) {
    const float t = __expf(-2.0f * x);
    return __fdividef(1.0f - t, 1.0f + t);
}

__global__ __launch_bounds__(NT, 1)
void encoder_rnn_spin(const int* __restrict__ basket,
                      const float* __restrict__ hidden,
                      const float* __restrict__ emb_table,
                      const float* __restrict__ w_ih,
                      const float* __restrict__ w_hh,
                      const float* __restrict__ b_ih,
                      const float* __restrict__ b_hh,
                      float* __restrict__ out,
                      int out_size)
{
    __shared__ float s_red[WARPS * H];      // producers: 16 KB gather rows
    __shared__ float s_gh[3 * H];           // tail: gh
    __shared__ float s_gi[3 * H];           // tail: gi
    __shared__ float s_h[H];

    const int tid  = threadIdx.x;
    const int lane = tid & 31;
    const int w    = tid >> 5;
    const int blk  = blockIdx.x;

    if (blk < GATHER_BLKS) {
        // ================= producers (identical to R2 fast path) =================
        const int item = blk * WARPS + w;
        float4 v = make_float4(0.f, 0.f, 0.f, 0.f);
        if (item < BASKET_LEN) {
            const long idx = (long)__ldg(&basket[item]);
            v = __ldg(&reinterpret_cast<const float4*>(emb_table)[idx * 32 + lane]);
        }
        reinterpret_cast<float4*>(s_red)[w * 32 + lane] = v;
        __syncthreads();
        if (tid < H) {
            float a0 = 0.f, a1 = 0.f, a2 = 0.f, a3 = 0.f;
            #pragma unroll
            for (int ww = 0; ww < WARPS; ww += 4) {
                a0 += s_red[(ww + 0) * H + tid];
                a1 += s_red[(ww + 1) * H + tid];
                a2 += s_red[(ww + 2) * H + tid];
                a3 += s_red[(ww + 3) * H + tid];
            }
            g_part[blk][tid] = (a0 + a1) + (a2 + a3);
        }
        __syncthreads();
        if (tid == 0) {
            unsigned old;
            asm volatile("atom.release.gpu.global.add.u32 %0, [%1], 1;"
                         : "=r"(old) : "l"(&g_ticket) : "memory");
        }
        return;
    }

    // ======================= dedicated tail (block 7) =======================
    const int r0 = w * 12;                  // 32 warps * 12 rows = 384

    // -- gh = w_hh @ h + b_hh (overlaps producers' gather) --
    {
        const float4 h4 = __ldg(&reinterpret_cast<const float4*>(hidden)[lane]);
        float p[12];
        #pragma unroll
        for (int j = 0; j < 12; j++) {
            const float4 a = __ldg(&reinterpret_cast<const float4*>(w_hh)[(size_t)(r0 + j) * 32 + lane]);
            p[j] = a.x * h4.x + a.y * h4.y + a.z * h4.z + a.w * h4.w;
        }
        #pragma unroll
        for (int off = 16; off; off >>= 1)
            #pragma unroll
            for (int j = 0; j < 12; j++)
                p[j] += __shfl_xor_sync(0xFFFFFFFFu, p[j], off);
        #pragma unroll
        for (int j = 0; j < 12; j++)
            if (lane == j) s_gh[r0 + j] = p[j] + __ldg(&b_hh[r0 + j]);
    }
    if (tid < H) s_h[tid] = __ldg(&hidden[tid]);

    // -- prefetch this warp's w_ih rows + biases into REGISTERS (off the wait path) --
    float4 wreg[12];
    float  breg[12];
    #pragma unroll
    for (int j = 0; j < 12; j++) {
        wreg[j] = __ldg(&reinterpret_cast<const float4*>(w_ih)[(size_t)(r0 + j) * 32 + lane]);
        breg[j] = __ldg(&b_ih[r0 + j]);
    }

    // -- spin until all 7 producers have published (acquire) --
    {
        unsigned t;
        do {
            asm volatile("ld.acquire.gpu.global.u32 %0, [%1];"
                         : "=r"(t) : "l"(&g_ticket) : "memory");
        } while (t != GATHER_BLKS);
    }

    // -- each warp privately combines partials -> emb4 (no smem, no extra bar) --
    float4 e4;
    {
        const float4* p4 = reinterpret_cast<const float4*>(g_part);   // [7][32] float4
        float4 s0 = p4[0 * 32 + lane];
        float4 s1 = p4[1 * 32 + lane];
        float4 s2 = p4[2 * 32 + lane];
        float4 s3 = p4[3 * 32 + lane];
        const float4 s4 = p4[4 * 32 + lane];
        const float4 s5 = p4[5 * 32 + lane];
        const float4 s6 = p4[6 * 32 + lane];
        s0.x += s1.x; s0.y += s1.y; s0.z += s1.z; s0.w += s1.w;
        s2.x += s3.x; s2.y += s3.y; s2.z += s3.z; s2.w += s3.w;
        s0.x += s2.x; s0.y += s2.y; s0.z += s2.z; s0.w += s2.w;
        s0.x += s4.x; s0.y += s4.y; s0.z += s4.z; s0.w += s4.w;
        s0.x += s5.x; s0.y += s5.y; s0.z += s5.z; s0.w += s5.w;
        s0.x += s6.x; s0.y += s6.y; s0.z += s6.z; s0.w += s6.w;
        const float inv = 1.0f / (float)H;
        e4 = make_float4(s0.x * inv, s0.y * inv, s0.z * inv, s0.w * inv);
    }

    // -- gi = w_ih @ emb + b_ih from registers --
    {
        float p[12];
        #pragma unroll
        for (int j = 0; j < 12; j++)
            p[j] = wreg[j].x * e4.x + wreg[j].y * e4.y + wreg[j].z * e4.z + wreg[j].w * e4.w;
        #pragma unroll
        for (int off = 16; off; off >>= 1)
            #pragma unroll
            for (int j = 0; j < 12; j++)
                p[j] += __shfl_xor_sync(0xFFFFFFFFu, p[j], off);
        #pragma unroll
        for (int j = 0; j < 12; j++)
            if (lane == j) s_gi[r0 + j] = p[j] + breg[j];
    }
    __syncthreads();

    // -- gates + replicated output --
    if (tid < H) {
        const float r = fast_sigmoid(s_gi[tid]         + s_gh[tid]);
        const float z = fast_sigmoid(s_gi[H + tid]     + s_gh[H + tid]);
        const float n = fast_tanh  (s_gi[2 * H + tid] + r * s_gh[2 * H + tid]);
        const float h_new = (1.0f - z) * n + z * s_h[tid];
        for (int o = tid; o < out_size; o += H)
            out[o] = h_new;
    }

    if (tid == 0) g_ticket = 0;   // reset for next graph replay
}

extern "C" void kernel_launch(void* const* d_in, const int* in_sizes, int n_in,
                              void* d_out, int out_size)
{
    const int*   basket    = (const int*)  d_in[0];
    const float* hidden    = (const float*)d_in[1];
    const float* emb_table = (const float*)d_in[2];
    const float* w_ih      = (const float*)d_in[3];
    const float* w_hh      = (const float*)d_in[4];
    const float* b_ih      = (const float*)d_in[5];
    const float* b_hh      = (const float*)d_in[6];
    float* out = (float*)d_out;

    encoder_rnn_spin<<<NB, NT>>>(basket, hidden, emb_table,
                                 w_ih, w_hh, b_ih, b_hh,
                                 out, out_size);
}

// round 10
// speedup vs baseline: 1.1622x; 1.1622x over previous
#include <cuda_runtime.h>
#include <cuda_bf16.h>

#define H            128
#define BASKET_LEN   200
#define NT           1024          // 32 warps per block
#define WARPS        32
#define GATHER_BLKS  7             // 7*32 = 224 warps >= 200 items
#define NB           (GATHER_BLKS + 1)   // +1 block for gh matvec

// Scratch (device globals; no allocation). All slots written every launch.
__device__ float        g_part[GATHER_BLKS][H];
__device__ float        g_gh[3 * H];
__device__ unsigned int g_ticket;   // zero at load; reset by last block each launch

__global__ __launch_bounds__(NT, 1)
void encoder_rnn_fused(const int* __restrict__ basket,
                       const float* __restrict__ hidden,
                       const float* __restrict__ emb_table,
                       const float* __restrict__ w_ih,
                       const float* __restrict__ w_hh,
                       const float* __restrict__ b_ih,
                       const float* __restrict__ b_hh,
                       float* __restrict__ out,
                       int out_size)
{
    __shared__ float s_red[WARPS * H];      // 16 KB: gather per-warp rows
    __shared__ float s_emb[H];
    __shared__ float s_gi[3 * H];
    __shared__ float s_h[H];
    __shared__ unsigned s_last;

    const int tid  = threadIdx.x;
    const int lane = tid & 31;
    const int w    = tid >> 5;
    const int blk  = blockIdx.x;

    if (blk < GATHER_BLKS) {
        // ---- Phase A: one warp per basket item, full 512B row per LDG.128 ----
        const int item = blk * WARPS + w;
        float4 v = make_float4(0.f, 0.f, 0.f, 0.f);
        if (item < BASKET_LEN) {
            const long idx = (long)__ldg(&basket[item]);
            v = __ldg(&reinterpret_cast<const float4*>(emb_table)[idx * 32 + lane]);
        }
        reinterpret_cast<float4*>(s_red)[w * 32 + lane] = v;
        __syncthreads();
        if (tid < H) {
            float a = 0.f;
            #pragma unroll
            for (int ww = 0; ww < WARPS; ww++) a += s_red[ww * H + tid];
            g_part[blk][tid] = a;
        }
    } else {
        // ---- Phase A': gh = w_hh @ h + b_hh (independent of gather) ----
        const float4 h4 = __ldg(&reinterpret_cast<const float4*>(hidden)[lane]);
        const int r0 = w * 12;                       // 32 warps * 12 rows = 384
        for (int rr = 0; rr < 12; rr += 4) {
            float p0, p1, p2, p3;
            {
                const float4 a = __ldg(&reinterpret_cast<const float4*>(w_hh)[(size_t)(r0 + rr + 0) * 32 + lane]);
                const float4 b = __ldg(&reinterpret_cast<const float4*>(w_hh)[(size_t)(r0 + rr + 1) * 32 + lane]);
                const float4 c = __ldg(&reinterpret_cast<const float4*>(w_hh)[(size_t)(r0 + rr + 2) * 32 + lane]);
                const float4 d = __ldg(&reinterpret_cast<const float4*>(w_hh)[(size_t)(r0 + rr + 3) * 32 + lane]);
                p0 = a.x * h4.x + a.y * h4.y + a.z * h4.z + a.w * h4.w;
                p1 = b.x * h4.x + b.y * h4.y + b.z * h4.z + b.w * h4.w;
                p2 = c.x * h4.x + c.y * h4.y + c.z * h4.z + c.w * h4.w;
                p3 = d.x * h4.x + d.y * h4.y + d.z * h4.z + d.w * h4.w;
            }
            #pragma unroll
            for (int off = 16; off; off >>= 1) {
                p0 += __shfl_xor_sync(0xFFFFFFFFu, p0, off);
                p1 += __shfl_xor_sync(0xFFFFFFFFu, p1, off);
                p2 += __shfl_xor_sync(0xFFFFFFFFu, p2, off);
                p3 += __shfl_xor_sync(0xFFFFFFFFu, p3, off);
            }
            if (lane == 0) {
                g_gh[r0 + rr + 0] = p0 + __ldg(&b_hh[r0 + rr + 0]);
                g_gh[r0 + rr + 1] = p1 + __ldg(&b_hh[r0 + rr + 1]);
                g_gh[r0 + rr + 2] = p2 + __ldg(&b_hh[r0 + rr + 2]);
                g_gh[r0 + rr + 3] = p3 + __ldg(&b_hh[r0 + rr + 3]);
            }
        }
    }

    // ---- Ticket: last-arriving block runs the tail ----
    __threadfence();
    __syncthreads();
    if (tid == 0) s_last = (atomicAdd(&g_ticket, 1u) == NB - 1);
    __syncthreads();
    if (!s_last) return;
    __threadfence();   // acquire: make peers' g_part / g_gh visible

    // ---- Phase B: reduce partials -> emb; load h ----
    if (tid < H) {
        float a = 0.f;
        #pragma unroll
        for (int b = 0; b < GATHER_BLKS; b++) a += g_part[b][tid];
        s_emb[tid] = a * (1.0f / (float)H);
        s_h[tid]   = hidden[tid];
    }
    __syncthreads();

    // ---- Phase C: gi = w_ih @ emb + b_ih (32 warps x 12 rows) ----
    {
        const float4 e4 = reinterpret_cast<const float4*>(s_emb)[lane];
        const int r0 = w * 12;
        for (int rr = 0; rr < 12; rr += 4) {
            float p0, p1, p2, p3;
            {
                const float4 a = __ldg(&reinterpret_cast<const float4*>(w_ih)[(size_t)(r0 + rr + 0) * 32 + lane]);
                const float4 b = __ldg(&reinterpret_cast<const float4*>(w_ih)[(size_t)(r0 + rr + 1) * 32 + lane]);
                const float4 c = __ldg(&reinterpret_cast<const float4*>(w_ih)[(size_t)(r0 + rr + 2) * 32 + lane]);
                const float4 d = __ldg(&reinterpret_cast<const float4*>(w_ih)[(size_t)(r0 + rr + 3) * 32 + lane]);
                p0 = a.x * e4.x + a.y * e4.y + a.z * e4.z + a.w * e4.w;
                p1 = b.x * e4.x + b.y * e4.y + b.z * e4.z + b.w * e4.w;
                p2 = c.x * e4.x + c.y * e4.y + c.z * e4.z + c.w * e4.w;
                p3 = d.x * e4.x + d.y * e4.y + d.z * e4.z + d.w * e4.w;
            }
            #pragma unroll
            for (int off = 16; off; off >>= 1) {
                p0 += __shfl_xor_sync(0xFFFFFFFFu, p0, off);
                p1 += __shfl_xor_sync(0xFFFFFFFFu, p1, off);
                p2 += __shfl_xor_sync(0xFFFFFFFFu, p2, off);
                p3 += __shfl_xor_sync(0xFFFFFFFFu, p3, off);
            }
            if (lane == 0) {
                s_gi[r0 + rr + 0] = p0 + __ldg(&b_ih[r0 + rr + 0]);
                s_gi[r0 + rr + 1] = p1 + __ldg(&b_ih[r0 + rr + 1]);
                s_gi[r0 + rr + 2] = p2 + __ldg(&b_ih[r0 + rr + 2]);
                s_gi[r0 + rr + 3] = p3 + __ldg(&b_ih[r0 + rr + 3]);
            }
        }
    }
    __syncthreads();

    // ---- Phase D: GRU gates + replicated output ----
    if (tid < H) {
        const float i_r = s_gi[tid];
        const float i_z = s_gi[H + tid];
        const float i_n = s_gi[2 * H + tid];
        const float h_r = g_gh[tid];
        const float h_z = g_gh[H + tid];
        const float h_n = g_gh[2 * H + tid];

        const float r = 1.0f / (1.0f + expf(-(i_r + h_r)));
        const float z = 1.0f / (1.0f + expf(-(i_z + h_z)));
        const float n = tanhf(i_n + r * h_n);
        const float h_new = (1.0f - z) * n + z * s_h[tid];

        for (int o = tid; o < out_size; o += H)
            out[o] = h_new;
    }

    if (tid == 0) g_ticket = 0;   // reset for next graph replay
}

extern "C" void kernel_launch(void* const* d_in, const int* in_sizes, int n_in,
                              void* d_out, int out_size)
{
    const int*   basket    = (const int*)  d_in[0];
    const float* hidden    = (const float*)d_in[1];
    const float* emb_table = (const float*)d_in[2];
    const float* w_ih      = (const float*)d_in[3];
    const float* w_hh      = (const float*)d_in[4];
    const float* b_ih      = (const float*)d_in[5];
    const float* b_hh      = (const float*)d_in[6];
    float* out = (float*)d_out;

    encoder_rnn_fused<<<NB, NT>>>(basket, hidden, emb_table,
                                  w_ih, w_hh, b_ih, b_hh,
                                  out, out_size);
}